// round 1
// baseline (speedup 1.0000x reference)
#include <cuda_runtime.h>

#define ADAPT  32
#define NBINS  32
#define T_LEN  2048
#define NCH    (T_LEN / ADAPT)   // 64 chunks per batch row
#define MAX_B  1024

// Scratch (static device globals: allocation-free, graph-safe)
__device__ float g_dot [MAX_B * T_LEN];   // per-element dot with quant_bins (8 MB)
__device__ float g_mdot[MAX_B * NCH];     // per-chunk mean(dot)
__device__ float g_mg  [MAX_B * NCH];     // per-chunk scale factor mean(g)

// ---------------------------------------------------------------------------
// Pass 1: one warp per 32x32 tile. Computes dot[s] = quant[s,:]·quant_bins,
// g[s] = quant[s,:]·change_scales; stores dot, mean(dot), mean(g).
// Carry-free -> fully parallel, DRAM-streaming bound.
// ---------------------------------------------------------------------------
__global__ void __launch_bounds__(256, 1)
k1_tiles(const float* __restrict__ x,
         const float* __restrict__ qb,
         const float* __restrict__ cs,
         int ntiles)
{
    __shared__ float4 tile4[8][32 * 8];   // 8 warps x (32 rows x 8 float4) = 32 KB
    __shared__ float4 s_qb[8];
    __shared__ float4 s_cs[8];

    const int tid = threadIdx.x;
    if (tid < 8)            s_qb[tid]     = reinterpret_cast<const float4*>(qb)[tid];
    else if (tid < 16)      s_cs[tid - 8] = reinterpret_cast<const float4*>(cs)[tid - 8];
    __syncthreads();

    const int w    = tid >> 5;
    const int lane = tid & 31;
    const int tile = blockIdx.x * 8 + w;
    if (tile >= ntiles) return;

    // Tile = 32 steps x 32 bins = 1024 contiguous floats = 256 float4
    const float4* xp = reinterpret_cast<const float4*>(x) + (size_t)tile * 256;

    float4 v[8];
#pragma unroll
    for (int k = 0; k < 8; k++) v[k] = xp[lane + 32 * k];

    // XOR-swizzled transpose store: float4 index f4 = lane + 32k
    //   row s = lane>>3 + 4k, col-quad j = lane&7, slot = j ^ (s&7)
    float4* tb = tile4[w];
#pragma unroll
    for (int k = 0; k < 8; k++) {
        const int s = (lane >> 3) + 4 * k;
        const int j = lane & 7;
        tb[s * 8 + (j ^ (s & 7))] = v[k];
    }
    __syncwarp();

    // lane = step s: read its row (conflict-free via same swizzle), two dot products
    const int s = lane;
    float dotv = 0.f, gv = 0.f;
#pragma unroll
    for (int j = 0; j < 8; j++) {
        const float4 q  = tb[s * 8 + (j ^ (s & 7))];
        const float4 b4 = s_qb[j];
        const float4 c4 = s_cs[j];
        dotv += q.x * b4.x + q.y * b4.y + q.z * b4.z + q.w * b4.w;
        gv   += q.x * c4.x + q.y * c4.y + q.z * c4.z + q.w * c4.w;
    }

    g_dot[(size_t)tile * ADAPT + lane] = dotv;

    float md = dotv, mgv = gv;
#pragma unroll
    for (int off = 16; off; off >>= 1) {
        md  += __shfl_xor_sync(0xffffffffu, md,  off);
        mgv += __shfl_xor_sync(0xffffffffu, mgv, off);
    }
    if (lane == 0) {
        g_mdot[tile] = md  * (1.f / ADAPT);
        g_mg[tile]   = mgv * (1.f / ADAPT);
    }
}

// ---------------------------------------------------------------------------
// Pass 2: one block per batch row. Warp 0 does an affine warp-scan of the
// 64-chunk recurrence (pred += S*mdot; S *= mg), then all 256 threads stream
// out[t] = P[c] + S[c]*dot[t].
// ---------------------------------------------------------------------------
__global__ void __launch_bounds__(256, 4)
k2_scan_apply(float* __restrict__ out)
{
    const int b   = blockIdx.x;
    const int tid = threadIdx.x;
    __shared__ float sP[NCH];   // pred entering chunk c (exclusive)
    __shared__ float sS[NCH];   // cumulative scale entering chunk c (exclusive)

    if (tid < 32) {
        const int lane = tid;
        // Each lane owns 2 consecutive chunks: c0 = 2*lane, c1 = 2*lane+1
        const float2 mdp = reinterpret_cast<const float2*>(g_mdot + b * NCH)[lane];
        const float2 mgp = reinterpret_cast<const float2*>(g_mg   + b * NCH)[lane];

        // Segment summary (g, d): entering state (S,P) -> (S*g, P + S*d)
        float g = mgp.x * mgp.y;
        float d = mdp.x + mgp.x * mdp.y;

        // Inclusive warp scan with affine composition
#pragma unroll
        for (int off = 1; off < 32; off <<= 1) {
            const float gp = __shfl_up_sync(0xffffffffu, g, off);
            const float dp = __shfl_up_sync(0xffffffffu, d, off);
            if (lane >= off) { d = dp + gp * d; g = gp * g; }
        }
        // Exclusive = shift by one lane
        float Se = __shfl_up_sync(0xffffffffu, g, 1);
        float Pe = __shfl_up_sync(0xffffffffu, d, 1);
        if (lane == 0) { Se = 1.f; Pe = 0.f; }

        sS[2 * lane]     = Se;
        sP[2 * lane]     = Pe;
        sS[2 * lane + 1] = Se * mgp.x;
        sP[2 * lane + 1] = Pe + Se * mdp.x;
    }
    __syncthreads();

    const float4* dp4 = reinterpret_cast<const float4*>(g_dot + (size_t)b * T_LEN);
    float4*       op4 = reinterpret_cast<float4*>(out + (size_t)b * T_LEN);
#pragma unroll
    for (int k = 0; k < T_LEN / (4 * 256); k++) {
        const int i4 = tid + 256 * k;      // float4 index; t = 4*i4
        const int c  = i4 >> 3;            // 8 float4 per 32-step chunk
        const float P = sP[c];
        const float S = sS[c];
        const float4 q = dp4[i4];
        float4 o;
        o.x = P + S * q.x;
        o.y = P + S * q.y;
        o.z = P + S * q.z;
        o.w = P + S * q.w;
        op4[i4] = o;
    }
}

// ---------------------------------------------------------------------------
extern "C" void kernel_launch(void* const* d_in, const int* in_sizes, int n_in,
                              void* d_out, int out_size)
{
    const float* x  = (const float*)d_in[0];   // (B, T, NB) fp32
    const float* qb = (const float*)d_in[1];   // (NB,)
    const float* cs = (const float*)d_in[2];   // (NB, 1)
    float* out      = (float*)d_out;           // (B, T) fp32

    const int ntiles = out_size / ADAPT;       // B * T / 32 tiles
    const int B      = out_size / T_LEN;

    k1_tiles<<<(ntiles + 7) / 8, 256>>>(x, qb, cs, ntiles);
    k2_scan_apply<<<B, 256>>>(out);
}